// round 1
// baseline (speedup 1.0000x reference)
#include <cuda_runtime.h>
#include <cstdint>

#define B_SZ 512
#define IN_F 512
#define OUT_F 100
#define KD 5
#define OC 500              // OUT_F * KD
#define LOG2E 1.4426950408889634f

// Scratch for M = (x @ T) * log2(e), laid out [b][o*5+k], 512x500 floats = 1MB
__device__ float g_M[B_SZ * OC];

__device__ __forceinline__ float ex2(float x) {
    float r;
    asm("ex2.approx.f32 %0, %1;" : "=f"(r) : "f"(x));
    return r;
}

// ---------------------------------------------------------------------------
// Kernel 1: M[b][oc] = sum_i x[b][i] * T[i][oc]  (then scale by log2e)
// Block: 128 threads, covers 8 b-rows x 128 oc-cols. Grid (64, 4).
// x tile staged in smem transposed as xs[i][bb] so inner loop reads 2x LDS.128
// (uniform broadcast) + 1 coalesced LDG of T per 8 FMAs.
// ---------------------------------------------------------------------------
__global__ void __launch_bounds__(128) gemm_kernel(const float* __restrict__ x,
                                                   const float* __restrict__ T) {
    __shared__ __align__(16) float xs[IN_F * 8];  // [i][bb], 16KB

    const int t = threadIdx.x;
    const int b0 = blockIdx.x * 8;
    const int oc0 = blockIdx.y * 128;

    // cooperative transpose load: x[b0+bb][i] -> xs[i*8+bb]
    for (int idx = t; idx < IN_F * 8; idx += 128) {
        int bb = idx >> 9;          // idx / 512
        int i = idx & (IN_F - 1);   // idx % 512
        xs[i * 8 + bb] = x[(b0 + bb) * IN_F + i];
    }
    __syncthreads();

    const int oc = oc0 + t;
    if (oc < OC) {
        float acc0 = 0.f, acc1 = 0.f, acc2 = 0.f, acc3 = 0.f;
        float acc4 = 0.f, acc5 = 0.f, acc6 = 0.f, acc7 = 0.f;
        const float* tp = T + oc;
#pragma unroll 4
        for (int i = 0; i < IN_F; i++) {
            float tv = tp[i * OC];
            float4 xa = *reinterpret_cast<const float4*>(xs + i * 8);
            float4 xb = *reinterpret_cast<const float4*>(xs + i * 8 + 4);
            acc0 += xa.x * tv; acc1 += xa.y * tv;
            acc2 += xa.z * tv; acc3 += xa.w * tv;
            acc4 += xb.x * tv; acc5 += xb.y * tv;
            acc6 += xb.z * tv; acc7 += xb.w * tv;
        }
        g_M[(b0 + 0) * OC + oc] = acc0 * LOG2E;
        g_M[(b0 + 1) * OC + oc] = acc1 * LOG2E;
        g_M[(b0 + 2) * OC + oc] = acc2 * LOG2E;
        g_M[(b0 + 3) * OC + oc] = acc3 * LOG2E;
        g_M[(b0 + 4) * OC + oc] = acc4 * LOG2E;
        g_M[(b0 + 5) * OC + oc] = acc5 * LOG2E;
        g_M[(b0 + 6) * OC + oc] = acc6 * LOG2E;
        g_M[(b0 + 7) * OC + oc] = acc7 * LOG2E;
    }
}

// ---------------------------------------------------------------------------
// Kernel 2: out[j][o] += sum_{i in split} exp2(-sum_k |M[i,o,k]-M[j,o,k]|)
// Block: 512 threads. Thread t (t<500): o = t%100, jl = t/100 in [0,5).
// Each thread serves 2 j's: j1 = jt*10+jl, j2 = j1+5  (JR=2 halves LDS traffic).
// i-range split in 8 (64 i's / block), staged in smem 16 rows at a time.
// Grid (52, 8). Requires out pre-zeroed; accumulates with atomicAdd.
// ---------------------------------------------------------------------------
__global__ void __launch_bounds__(512) md_kernel(float* __restrict__ out) {
    __shared__ __align__(16) float ms[16 * OC];  // 32KB

    const int t = threadIdx.x;
    const int jt = blockIdx.x;
    const int i0 = blockIdx.y * 64;

    const int o = t % 100;
    const int jl = t / 100;
    const bool act = (t < 500);
    const int j1 = jt * 10 + jl;
    const int j2 = j1 + 5;
    const bool v1 = act && (j1 < B_SZ);
    const bool v2 = act && (j2 < B_SZ);

    float a0 = 0.f, a1 = 0.f, a2 = 0.f, a3 = 0.f, a4 = 0.f;
    float b0 = 0.f, b1 = 0.f, b2 = 0.f, b3 = 0.f, b4 = 0.f;
    if (v1) {
        const float* m = g_M + j1 * OC + o * KD;
        a0 = m[0]; a1 = m[1]; a2 = m[2]; a3 = m[3]; a4 = m[4];
    }
    if (v2) {
        const float* m = g_M + j2 * OC + o * KD;
        b0 = m[0]; b1 = m[1]; b2 = m[2]; b3 = m[3]; b4 = m[4];
    }

    float acc1 = 0.f, acc2 = 0.f;

    for (int c = 0; c < 4; c++) {
        const int ib = i0 + c * 16;
        __syncthreads();
        // stage 16 rows (8000 floats = 2000 float4) of M into smem
        {
            const float4* src = reinterpret_cast<const float4*>(g_M + ib * OC);
            float4* dst = reinterpret_cast<float4*>(ms);
            for (int idx = t; idx < 2000; idx += 512) dst[idx] = src[idx];
        }
        __syncthreads();

        if (act) {
#pragma unroll
            for (int ii = 0; ii < 16; ii++) {
                const float* m = ms + ii * OC + o * KD;  // stride-5: conflict-free
                float d0 = m[0], d1 = m[1], d2 = m[2], d3 = m[3], d4 = m[4];
                {
                    float p = -fabsf(d0 - a0) - fabsf(d1 - a1);
                    float q = -fabsf(d2 - a2) - fabsf(d3 - a3);
                    float n = (p + q) - fabsf(d4 - a4);
                    acc1 += ex2(n);
                }
                {
                    float p = -fabsf(d0 - b0) - fabsf(d1 - b1);
                    float q = -fabsf(d2 - b2) - fabsf(d3 - b3);
                    float n = (p + q) - fabsf(d4 - b4);
                    acc2 += ex2(n);
                }
            }
        }
    }

    // remove self-term (exp(0)=1) exactly once, in the owning i-split
    if (v1) {
        if (j1 >= i0 && j1 < i0 + 64) acc1 -= 1.0f;
        atomicAdd(&out[j1 * OUT_F + o], acc1);
    }
    if (v2) {
        if (j2 >= i0 && j2 < i0 + 64) acc2 -= 1.0f;
        atomicAdd(&out[j2 * OUT_F + o], acc2);
    }
}

extern "C" void kernel_launch(void* const* d_in, const int* in_sizes, int n_in,
                              void* d_out, int out_size) {
    const float* x = (const float*)d_in[0];   // [512, 512]
    const float* T = (const float*)d_in[1];   // [512, 100, 5] -> [512, 500]
    float* out = (float*)d_out;               // [512, 100]

    cudaMemsetAsync(out, 0, (size_t)out_size * sizeof(float));
    gemm_kernel<<<dim3(64, 4), 128>>>(x, T);
    md_kernel<<<dim3(52, 8), 512>>>(out);
}

// round 2
// speedup vs baseline: 1.4381x; 1.4381x over previous
#include <cuda_runtime.h>
#include <cstdint>

#define B_SZ 512
#define IN_F 512
#define OUT_F 100
#define KD 5
#define OC 500              // OUT_F * KD
#define LOG2E 1.4426950408889634f

// Scratch for M = (x @ T) * log2(e), laid out [b][o*5+k], 512x500 floats = 1MB
__device__ float g_M[B_SZ * OC];

__device__ __forceinline__ float ex2(float x) {
    float r;
    asm("ex2.approx.f32 %0, %1;" : "=f"(r) : "f"(x));
    return r;
}

// ---------------------------------------------------------------------------
// Kernel 1: M[b][oc] = sum_i x[b][i] * T[i][oc], scaled by log2e.
// Block: 256 threads = 128 oc-lanes x 2 K-halves (kh). Each thread accumulates
// 8 b-rows over its 256-long K-half; halves reduced through smem.
// Grid (64, 4) -> 256 blocks, 2048 warps (~3.5/SMSP) so L2-hit LDG latency is
// covered and the fma pipe saturates.
// ---------------------------------------------------------------------------
__global__ void __launch_bounds__(256) gemm_kernel(const float* __restrict__ x,
                                                   const float* __restrict__ T) {
    __shared__ __align__(16) float xs[IN_F * 8];   // [i][bb], 16KB
    __shared__ __align__(16) float red[8 * 128];   // partial sums, 4KB

    const int t = threadIdx.x;
    const int oc_lane = t & 127;
    const int kh = t >> 7;
    const int b0 = blockIdx.x * 8;
    const int oc0 = blockIdx.y * 128;
    const int oc = oc0 + oc_lane;

    // cooperative transpose load: x[b0+bb][i] -> xs[i*8+bb]
    for (int idx = t; idx < IN_F * 8; idx += 256) {
        int bb = idx >> 9;
        int i = idx & (IN_F - 1);
        xs[i * 8 + bb] = x[(b0 + bb) * IN_F + i];
    }
    __syncthreads();

    float acc0 = 0.f, acc1 = 0.f, acc2 = 0.f, acc3 = 0.f;
    float acc4 = 0.f, acc5 = 0.f, acc6 = 0.f, acc7 = 0.f;

    if (oc < OC) {
        const float* tp = T + (size_t)(kh * 256) * OC + oc;
        const float* xp = xs + kh * 256 * 8;
#pragma unroll 8
        for (int i = 0; i < 256; i++) {
            float tv = tp[i * OC];
            float4 xa = *reinterpret_cast<const float4*>(xp + i * 8);
            float4 xb = *reinterpret_cast<const float4*>(xp + i * 8 + 4);
            acc0 += xa.x * tv; acc1 += xa.y * tv;
            acc2 += xa.z * tv; acc3 += xa.w * tv;
            acc4 += xb.x * tv; acc5 += xb.y * tv;
            acc6 += xb.z * tv; acc7 += xb.w * tv;
        }
    }

    if (kh == 1) {
        red[0 * 128 + oc_lane] = acc0;
        red[1 * 128 + oc_lane] = acc1;
        red[2 * 128 + oc_lane] = acc2;
        red[3 * 128 + oc_lane] = acc3;
        red[4 * 128 + oc_lane] = acc4;
        red[5 * 128 + oc_lane] = acc5;
        red[6 * 128 + oc_lane] = acc6;
        red[7 * 128 + oc_lane] = acc7;
    }
    __syncthreads();
    if (kh == 0 && oc < OC) {
        g_M[(b0 + 0) * OC + oc] = (acc0 + red[0 * 128 + oc_lane]) * LOG2E;
        g_M[(b0 + 1) * OC + oc] = (acc1 + red[1 * 128 + oc_lane]) * LOG2E;
        g_M[(b0 + 2) * OC + oc] = (acc2 + red[2 * 128 + oc_lane]) * LOG2E;
        g_M[(b0 + 3) * OC + oc] = (acc3 + red[3 * 128 + oc_lane]) * LOG2E;
        g_M[(b0 + 4) * OC + oc] = (acc4 + red[4 * 128 + oc_lane]) * LOG2E;
        g_M[(b0 + 5) * OC + oc] = (acc5 + red[5 * 128 + oc_lane]) * LOG2E;
        g_M[(b0 + 6) * OC + oc] = (acc6 + red[6 * 128 + oc_lane]) * LOG2E;
        g_M[(b0 + 7) * OC + oc] = (acc7 + red[7 * 128 + oc_lane]) * LOG2E;
    }
}

// ---------------------------------------------------------------------------
// Kernel 2: out[j][o] += sum_{i in split} exp2(-sum_k |M[i,o,k]-M[j,o,k]|)
// Block: 512 threads. Thread t (t<500): o = t%100, jl = t/100 in [0,5).
// JR=4: each thread serves j = jt*20 + jl + 5r, r in [0,4) — d-row LDS and
// loop overhead amortize over 4 exp-results. i-range split in 16 (32 i's per
// block), staged 16 rows at a time in smem. Grid (26, 16). atomicAdd into
// pre-zeroed out.
// ---------------------------------------------------------------------------
__global__ void __launch_bounds__(512) md_kernel(float* __restrict__ out) {
    __shared__ __align__(16) float ms[16 * OC];  // 32KB

    const int t = threadIdx.x;
    const int jt = blockIdx.x;
    const int i0 = blockIdx.y * 32;

    const int o = t % 100;
    const int jl = t / 100;
    const bool act = (t < 500);

    int jv[4];
    bool valid[4];
    float a[4][5];
    float acc[4];
#pragma unroll
    for (int r = 0; r < 4; r++) {
        jv[r] = jt * 20 + jl + 5 * r;
        valid[r] = act && (jv[r] < B_SZ);
        acc[r] = 0.f;
        if (valid[r]) {
            const float* m = g_M + jv[r] * OC + o * KD;
            a[r][0] = m[0]; a[r][1] = m[1]; a[r][2] = m[2];
            a[r][3] = m[3]; a[r][4] = m[4];
        } else {
            a[r][0] = a[r][1] = a[r][2] = a[r][3] = a[r][4] = 0.f;
        }
    }

    for (int c = 0; c < 2; c++) {
        const int ib = i0 + c * 16;
        __syncthreads();
        // stage 16 rows (8000 floats = 2000 float4) of M into smem
        {
            const float4* src = reinterpret_cast<const float4*>(g_M + ib * OC);
            float4* dst = reinterpret_cast<float4*>(ms);
            for (int idx = t; idx < 2000; idx += 512) dst[idx] = src[idx];
        }
        __syncthreads();

        if (act) {
#pragma unroll
            for (int ii = 0; ii < 16; ii++) {
                const float* m = ms + ii * OC + o * KD;  // stride-5: conflict-free
                float d0 = m[0], d1 = m[1], d2 = m[2], d3 = m[3], d4 = m[4];
#pragma unroll
                for (int r = 0; r < 4; r++) {
                    float p = -fabsf(d0 - a[r][0]) - fabsf(d1 - a[r][1]);
                    float q = -fabsf(d2 - a[r][2]) - fabsf(d3 - a[r][3]);
                    float n = (p + q) - fabsf(d4 - a[r][4]);
                    acc[r] += ex2(n);
                }
            }
        }
    }

    // remove self-term (exp(0)=1) exactly once, in the owning i-split
#pragma unroll
    for (int r = 0; r < 4; r++) {
        if (valid[r]) {
            if (jv[r] >= i0 && jv[r] < i0 + 32) acc[r] -= 1.0f;
            atomicAdd(&out[jv[r] * OUT_F + o], acc[r]);
        }
    }
}

extern "C" void kernel_launch(void* const* d_in, const int* in_sizes, int n_in,
                              void* d_out, int out_size) {
    const float* x = (const float*)d_in[0];   // [512, 512]
    const float* T = (const float*)d_in[1];   // [512, 100, 5] -> [512, 500]
    float* out = (float*)d_out;               // [512, 100]

    cudaMemsetAsync(out, 0, (size_t)out_size * sizeof(float));
    gemm_kernel<<<dim3(64, 4), 256>>>(x, T);
    md_kernel<<<dim3(26, 16), 512>>>(out);
}

// round 3
// speedup vs baseline: 1.7853x; 1.2414x over previous
#include <cuda_runtime.h>
#include <cstdint>

#define B_SZ 512
#define IN_F 512
#define OUT_F 100
#define KD 5
#define OC 500              // OUT_F * KD
#define LOG2E 1.4426950408889634f
#define NT 32               // number of batch tiles
#define TS 16               // tile size (NT*TS = B_SZ)

// Scratch for M = (x @ T) * log2(e), laid out [b][o*5+k], 512x500 floats = 1MB
__device__ float g_M[B_SZ * OC];

__device__ __forceinline__ float ex2(float x) {
    float r;
    asm("ex2.approx.f32 %0, %1;" : "=f"(r) : "f"(x));
    return r;
}

// ---------------------------------------------------------------------------
// Kernel 1: M[b][oc] = sum_i x[b][i] * T[i][oc], scaled by log2e.
// Block: 512 threads = 128 oc-lanes x 4 K-quarters (kh). Each thread
// accumulates 8 b-rows over its 128-long K-quarter; quarters reduced through
// smem. Grid (64, 4) -> 256 blocks x 16 warps = 4096 warps for latency cover.
// Also zeroes `out` (blocks with blockIdx.y == 0) so no separate memset.
// ---------------------------------------------------------------------------
__global__ void __launch_bounds__(512) gemm_kernel(const float* __restrict__ x,
                                                   const float* __restrict__ T,
                                                   float* __restrict__ out) {
    __shared__ __align__(16) float xs[IN_F * 8];     // [i][bb], 16KB
    __shared__ __align__(16) float red[3 * 8 * 128]; // partials from kh=1..3, 12KB

    const int t = threadIdx.x;
    const int oc_lane = t & 127;
    const int kh = t >> 7;                 // 0..3
    const int b0 = blockIdx.x * 8;
    const int oc0 = blockIdx.y * 128;
    const int oc = oc0 + oc_lane;

    // zero the output (512*100 floats) using the y==0 slice of the grid
    if (blockIdx.y == 0) {
        for (int idx = blockIdx.x * 512 + t; idx < B_SZ * OUT_F; idx += 64 * 512)
            out[idx] = 0.0f;
    }

    // cooperative transpose load: x[b0+bb][i] -> xs[i*8+bb]
    for (int idx = t; idx < IN_F * 8; idx += 512) {
        int bb = idx >> 9;
        int i = idx & (IN_F - 1);
        xs[i * 8 + bb] = x[(b0 + bb) * IN_F + i];
    }
    __syncthreads();

    float acc0 = 0.f, acc1 = 0.f, acc2 = 0.f, acc3 = 0.f;
    float acc4 = 0.f, acc5 = 0.f, acc6 = 0.f, acc7 = 0.f;

    if (oc < OC) {
        const float* tp = T + (size_t)(kh * 128) * OC + oc;
        const float* xp = xs + kh * 128 * 8;
#pragma unroll 8
        for (int i = 0; i < 128; i++) {
            float tv = tp[i * OC];
            float4 xa = *reinterpret_cast<const float4*>(xp + i * 8);
            float4 xb = *reinterpret_cast<const float4*>(xp + i * 8 + 4);
            acc0 += xa.x * tv; acc1 += xa.y * tv;
            acc2 += xa.z * tv; acc3 += xa.w * tv;
            acc4 += xb.x * tv; acc5 += xb.y * tv;
            acc6 += xb.z * tv; acc7 += xb.w * tv;
        }
    }

    if (kh > 0) {
        float* rp = red + (kh - 1) * 1024 + oc_lane;
        rp[0 * 128] = acc0; rp[1 * 128] = acc1;
        rp[2 * 128] = acc2; rp[3 * 128] = acc3;
        rp[4 * 128] = acc4; rp[5 * 128] = acc5;
        rp[6 * 128] = acc6; rp[7 * 128] = acc7;
    }
    __syncthreads();
    if (kh == 0 && oc < OC) {
        const float* r0 = red + oc_lane;
        const float* r1 = red + 1024 + oc_lane;
        const float* r2 = red + 2048 + oc_lane;
        g_M[(b0 + 0) * OC + oc] = (acc0 + r0[0]   + r1[0]   + r2[0])   * LOG2E;
        g_M[(b0 + 1) * OC + oc] = (acc1 + r0[128] + r1[128] + r2[128]) * LOG2E;
        g_M[(b0 + 2) * OC + oc] = (acc2 + r0[256] + r1[256] + r2[256]) * LOG2E;
        g_M[(b0 + 3) * OC + oc] = (acc3 + r0[384] + r1[384] + r2[384]) * LOG2E;
        g_M[(b0 + 4) * OC + oc] = (acc4 + r0[512] + r1[512] + r2[512]) * LOG2E;
        g_M[(b0 + 5) * OC + oc] = (acc5 + r0[640] + r1[640] + r2[640]) * LOG2E;
        g_M[(b0 + 6) * OC + oc] = (acc6 + r0[768] + r1[768] + r2[768]) * LOG2E;
        g_M[(b0 + 7) * OC + oc] = (acc7 + r0[896] + r1[896] + r2[896]) * LOG2E;
    }
}

// ---------------------------------------------------------------------------
// Kernel 2 (symmetric): one block per unordered tile pair (ta <= tb),
// tiles of 16 rows, 32 tiles -> 528 blocks.
// Block 416 threads; t<400 active: o = t>>2, jl = t&3. Each thread holds
// 4 j-rows (j = tb*16 + jl + 4r) in regs; i-rows of tile_a staged in smem.
// Per (i, o): e(i,j) accumulated into accJ[r] (-> out[j]); the transpose
// contribution sum_j e is reduced across the 4 jl-lanes via shfl.bfly and
// REDG'd into out[i] (off-diagonal pairs only).
// Diagonal blocks cover the full 16x16 within-tile grid via accJ and
// subtract the self-term exp(0)=1.
// ---------------------------------------------------------------------------
__global__ void __launch_bounds__(416, 3) md_kernel(float* __restrict__ out) {
    __shared__ __align__(16) float ms[TS * OC];  // 32KB

    // decode blockIdx.x -> (ta, tb), upper triangle row-major
    int rem = blockIdx.x;
    int ta = 0;
    while (rem >= NT - ta) { rem -= NT - ta; ta++; }
    const int tb = ta + rem;
    const bool diag = (ta == tb);

    const int t = threadIdx.x;
    const bool act = (t < 400);
    const int o = act ? (t >> 2) : 99;   // clamp for safe smem/gmem reads
    const int jl = t & 3;

    // stage tile_a: 16 rows x 500 floats = 2000 float4
    {
        const float4* src = reinterpret_cast<const float4*>(g_M + (size_t)ta * TS * OC);
        float4* dst = reinterpret_cast<float4*>(ms);
        for (int i = t; i < 2000; i += 416) dst[i] = src[i];
    }

    // load j-side rows into registers
    float a[4][5];
    float accJ[4];
#pragma unroll
    for (int r = 0; r < 4; r++) {
        const int j = tb * TS + jl + 4 * r;       // < 512 always
        const float* m = g_M + (size_t)j * OC + o * KD;
        a[r][0] = m[0]; a[r][1] = m[1]; a[r][2] = m[2];
        a[r][3] = m[3]; a[r][4] = m[4];
        accJ[r] = 0.f;
    }
    __syncthreads();

#pragma unroll
    for (int ii = 0; ii < TS; ii++) {
        const float* m = ms + ii * OC + o * KD;
        float d0 = m[0], d1 = m[1], d2 = m[2], d3 = m[3], d4 = m[4];
        float loc = 0.f;
#pragma unroll
        for (int r = 0; r < 4; r++) {
            float p = -fabsf(d0 - a[r][0]) - fabsf(d1 - a[r][1]);
            float q = -fabsf(d2 - a[r][2]) - fabsf(d3 - a[r][3]);
            float n = (p + q) - fabsf(d4 - a[r][4]);
            float e = ex2(n);
            accJ[r] += e;
            loc += e;
        }
        if (!diag) {
            // reduce sum over the 16 j's of this block across the 4 jl-lanes
            loc += __shfl_xor_sync(0xffffffffu, loc, 1);
            loc += __shfl_xor_sync(0xffffffffu, loc, 2);
            if (act && jl == 0)
                atomicAdd(&out[(ta * TS + ii) * OUT_F + o], loc);
        }
    }

    if (act) {
#pragma unroll
        for (int r = 0; r < 4; r++) {
            float v = accJ[r] - (diag ? 1.0f : 0.0f);
            atomicAdd(&out[(tb * TS + jl + 4 * r) * OUT_F + o], v);
        }
    }
}

extern "C" void kernel_launch(void* const* d_in, const int* in_sizes, int n_in,
                              void* d_out, int out_size) {
    const float* x = (const float*)d_in[0];   // [512, 512]
    const float* T = (const float*)d_in[1];   // [512, 100, 5] -> [512, 500]
    float* out = (float*)d_out;               // [512, 100]

    gemm_kernel<<<dim3(64, 4), 512>>>(x, T, out);
    md_kernel<<<NT * (NT + 1) / 2, 416>>>(out);  // 528 blocks
}

// round 4
// speedup vs baseline: 1.9389x; 1.0860x over previous
#include <cuda_runtime.h>
#include <cstdint>

#define B_SZ 512
#define IN_F 512
#define OUT_F 100
#define KD 5
#define OC 500              // OUT_F * KD
#define LOG2E 1.4426950408889634f
#define NT 32               // number of batch tiles
#define TS 16               // tile size (NT*TS = B_SZ)

// Scratch for M = (x @ T) * log2(e), laid out [b][o*5+k], 512x500 floats = 1MB
__device__ float g_M[B_SZ * OC];

__device__ __forceinline__ float ex2(float x) {
    float r;
    asm("ex2.approx.f32 %0, %1;" : "=f"(r) : "f"(x));
    return r;
}

// ---------------------------------------------------------------------------
// Kernel 1: M[b][oc] = sum_i x[b][i] * T[i][oc], scaled by log2e.
// Block: 512 threads = 64 oc-pair-lanes x 8 K-slices (kh). Each thread owns
// 8 b-rows x 2 consecutive oc (float2 T loads) over a 64-long K-slice;
// slices reduced through smem. Grid (64, 4) -> 256 blocks x 16 warps = 4096
// warps (~27/SM). Per-iter: 1 LDG.64 + 2 broadcast LDS.128 + 16 FFMA.
// Also zeroes `out` (blocks with blockIdx.y == 0).
// ---------------------------------------------------------------------------
__global__ void __launch_bounds__(512) gemm_kernel(const float* __restrict__ x,
                                                   const float* __restrict__ T,
                                                   float* __restrict__ out) {
    __shared__ __align__(16) float xs[IN_F * 8];          // [i][bb], 16KB
    __shared__ __align__(16) float red[7 * 8 * 128];      // kh=1..7 partials, 28KB

    const int t = threadIdx.x;
    const int lane = t & 63;               // oc-pair lane: covers oc0+lane*2, +1
    const int kh = t >> 6;                 // 0..7
    const int b0 = blockIdx.x * 8;
    const int oc0 = blockIdx.y * 128;
    const int oc = oc0 + lane * 2;
    const bool ocv = (oc < OC);            // oc+1 < OC too since OC is even

    if (blockIdx.y == 0) {
        for (int idx = blockIdx.x * 512 + t; idx < B_SZ * OUT_F; idx += 64 * 512)
            out[idx] = 0.0f;
    }

    // cooperative transpose load: x[b0+bb][i] -> xs[i*8+bb]
    for (int idx = t; idx < IN_F * 8; idx += 512) {
        int bb = idx >> 9;
        int i = idx & (IN_F - 1);
        xs[i * 8 + bb] = x[(b0 + bb) * IN_F + i];
    }
    __syncthreads();

    float accx[8] = {0.f, 0.f, 0.f, 0.f, 0.f, 0.f, 0.f, 0.f};
    float accy[8] = {0.f, 0.f, 0.f, 0.f, 0.f, 0.f, 0.f, 0.f};

    if (ocv) {
        const float* tp = T + (size_t)(kh * 64) * OC + oc;
        const float* xp = xs + kh * 64 * 8;
#pragma unroll 8
        for (int i = 0; i < 64; i++) {
            float2 tv = *reinterpret_cast<const float2*>(tp + i * OC);
            float4 xa = *reinterpret_cast<const float4*>(xp + i * 8);
            float4 xb = *reinterpret_cast<const float4*>(xp + i * 8 + 4);
            accx[0] += xa.x * tv.x; accy[0] += xa.x * tv.y;
            accx[1] += xa.y * tv.x; accy[1] += xa.y * tv.y;
            accx[2] += xa.z * tv.x; accy[2] += xa.z * tv.y;
            accx[3] += xa.w * tv.x; accy[3] += xa.w * tv.y;
            accx[4] += xb.x * tv.x; accy[4] += xb.x * tv.y;
            accx[5] += xb.y * tv.x; accy[5] += xb.y * tv.y;
            accx[6] += xb.z * tv.x; accy[6] += xb.z * tv.y;
            accx[7] += xb.w * tv.x; accy[7] += xb.w * tv.y;
        }
    }

    if (kh > 0) {
        float* rp = red + (kh - 1) * 1024 + lane * 2;
#pragma unroll
        for (int bb = 0; bb < 8; bb++) {
            rp[bb * 128 + 0] = accx[bb];
            rp[bb * 128 + 1] = accy[bb];
        }
    }
    __syncthreads();
    if (kh == 0 && ocv) {
#pragma unroll
        for (int bb = 0; bb < 8; bb++) {
            float sx = accx[bb], sy = accy[bb];
#pragma unroll
            for (int s = 0; s < 7; s++) {
                sx += red[s * 1024 + bb * 128 + lane * 2 + 0];
                sy += red[s * 1024 + bb * 128 + lane * 2 + 1];
            }
            float2 o2;
            o2.x = sx * LOG2E;
            o2.y = sy * LOG2E;
            *reinterpret_cast<float2*>(&g_M[(size_t)(b0 + bb) * OC + oc]) = o2;
        }
    }
}

// ---------------------------------------------------------------------------
// Kernel 2 (symmetric): one block per unordered tile pair (ta <= tb),
// tiles of 16 rows, 32 tiles -> 528 blocks.
// Block 416 threads; t<400 active: o = t>>2, jl = t&3. Each thread holds
// 4 j-rows in regs; i-rows of tile_a staged in smem. Per (i, o): e(i,j)
// accumulated into accJ[r] (-> out[j]); transpose contribution reduced across
// the 4 jl-lanes via shfl.bfly and atomically added into out[i].
// launch_bounds(416,2): 78-reg budget, no spills in the hot loop.
// ---------------------------------------------------------------------------
__global__ void __launch_bounds__(416, 2) md_kernel(float* __restrict__ out) {
    __shared__ __align__(16) float ms[TS * OC];  // 32KB

    // decode blockIdx.x -> (ta, tb), upper triangle row-major
    int rem = blockIdx.x;
    int ta = 0;
    while (rem >= NT - ta) { rem -= NT - ta; ta++; }
    const int tb = ta + rem;
    const bool diag = (ta == tb);

    const int t = threadIdx.x;
    const bool act = (t < 400);
    const int o = act ? (t >> 2) : 99;   // clamp for safe reads
    const int jl = t & 3;

    // stage tile_a: 16 rows x 500 floats = 2000 float4
    {
        const float4* src = reinterpret_cast<const float4*>(g_M + (size_t)ta * TS * OC);
        float4* dst = reinterpret_cast<float4*>(ms);
        for (int i = t; i < 2000; i += 416) dst[i] = src[i];
    }

    // load j-side rows into registers
    float a[4][5];
    float accJ[4];
#pragma unroll
    for (int r = 0; r < 4; r++) {
        const int j = tb * TS + jl + 4 * r;       // < 512 always
        const float* m = g_M + (size_t)j * OC + o * KD;
        a[r][0] = m[0]; a[r][1] = m[1]; a[r][2] = m[2];
        a[r][3] = m[3]; a[r][4] = m[4];
        accJ[r] = 0.f;
    }
    __syncthreads();

#pragma unroll
    for (int ii = 0; ii < TS; ii++) {
        const float* m = ms + ii * OC + o * KD;  // stride-5: conflict-free
        float d0 = m[0], d1 = m[1], d2 = m[2], d3 = m[3], d4 = m[4];
        float loc = 0.f;
#pragma unroll
        for (int r = 0; r < 4; r++) {
            float p = -fabsf(d0 - a[r][0]) - fabsf(d1 - a[r][1]);
            float q = -fabsf(d2 - a[r][2]) - fabsf(d3 - a[r][3]);
            float n = (p + q) - fabsf(d4 - a[r][4]);
            float e = ex2(n);
            accJ[r] += e;
            loc += e;
        }
        if (!diag) {
            loc += __shfl_xor_sync(0xffffffffu, loc, 1);
            loc += __shfl_xor_sync(0xffffffffu, loc, 2);
            if (act && jl == 0)
                atomicAdd(&out[(ta * TS + ii) * OUT_F + o], loc);
        }
    }

    if (act) {
#pragma unroll
        for (int r = 0; r < 4; r++) {
            float v = accJ[r] - (diag ? 1.0f : 0.0f);
            atomicAdd(&out[(tb * TS + jl + 4 * r) * OUT_F + o], v);
        }
    }
}

extern "C" void kernel_launch(void* const* d_in, const int* in_sizes, int n_in,
                              void* d_out, int out_size) {
    const float* x = (const float*)d_in[0];   // [512, 512]
    const float* T = (const float*)d_in[1];   // [512, 100, 5] -> [512, 500]
    float* out = (float*)d_out;               // [512, 100]

    gemm_kernel<<<dim3(64, 4), 512>>>(x, T, out);
    md_kernel<<<NT * (NT + 1) / 2, 416>>>(out);  // 528 blocks
}